// round 10
// baseline (speedup 1.0000x reference)
#include <cuda_runtime.h>
#include <cuda_bf16.h>

// loss_i = (label_i == label[N-1]) ? d2 : max(0, MARGIN - d2),  d2 = ||p_{N-1}-p_i||^2, D=3
// Output: scalar sum. SINGLE graph node: 8 CTAs x 1024 threads. CTAs 1..7
// publish partials via relaxed-RED + release arrival-count; CTA0 spin-waits
// (overlapped with its own work finishing), combines, writes out[0], resets
// globals for the next replay. No zero pass, no fences, allocation-free,
// graph-capturable, deterministic work every call.

#define MARGIN 500.0f
#define TPB 1024
#define NBLOCKS 8
#define PTS_PER_THREAD 4

__device__ float        g_accum = 0.0f;
__device__ unsigned int g_count = 0u;

__device__ __forceinline__ void red_add_f32_relaxed(float* p, float v) {
    asm volatile("red.relaxed.gpu.add.f32 [%0], %1;" :: "l"(p), "f"(v) : "memory");
}
__device__ __forceinline__ void red_add_u32_release(unsigned* p, unsigned v) {
    asm volatile("red.release.gpu.add.u32 [%0], %1;" :: "l"(p), "r"(v) : "memory");
}
__device__ __forceinline__ unsigned ld_u32_acquire(const unsigned* p) {
    unsigned v;
    asm volatile("ld.acquire.gpu.u32 %0, [%1];" : "=r"(v) : "l"(p) : "memory");
    return v;
}
__device__ __forceinline__ float ld_f32_relaxed(const float* p) {
    float v;
    asm volatile("ld.relaxed.gpu.f32 %0, [%1];" : "=f"(v) : "l"(p) : "memory");
    return v;
}
__device__ __forceinline__ void st_u32_relaxed(unsigned* p, unsigned v) {
    asm volatile("st.relaxed.gpu.u32 [%0], %1;" :: "l"(p), "r"(v) : "memory");
}
__device__ __forceinline__ void st_f32_relaxed(float* p, float v) {
    asm volatile("st.relaxed.gpu.f32 [%0], %1;" :: "l"(p), "f"(v) : "memory");
}

__global__ __launch_bounds__(TPB)
void contrastive_last_anchor_kernel(const int* __restrict__ labels,
                                    const float* __restrict__ coords,
                                    float* __restrict__ out,
                                    int n)
{
    // Anchor: same 2 cache lines chip-wide -> broadcast.
    const int   al = __ldg(labels + (n - 1));
    const float ax = __ldg(coords + 3 * (n - 1) + 0);
    const float ay = __ldg(coords + 3 * (n - 1) + 1);
    const float az = __ldg(coords + 3 * (n - 1) + 2);

    const int stride_pts = NBLOCKS * TPB * PTS_PER_THREAD;   // 32768
    float v = 0.0f;

    // Grid-stride over 4-point chunks (exactly one iteration for n = 32768).
    for (int base = (blockIdx.x * TPB + threadIdx.x) * PTS_PER_THREAD;
         base < n; base += stride_pts)
    {
        if (base + PTS_PER_THREAD <= n) {
            const int4   lab = *reinterpret_cast<const int4*>(labels + base);
            const float4* cp = reinterpret_cast<const float4*>(coords + 3 * base);
            const float4 c0 = cp[0], c1 = cp[1], c2 = cp[2];
            // p0=(c0.x,c0.y,c0.z) p1=(c0.w,c1.x,c1.y) p2=(c1.z,c1.w,c2.x) p3=(c2.y,c2.z,c2.w)
            {
                const float dx = ax - c0.x, dy = ay - c0.y, dz = az - c0.z;
                const float d2 = fmaf(dx, dx, fmaf(dy, dy, dz * dz));
                v += (lab.x == al) ? d2 : fmaxf(0.0f, MARGIN - d2);
            }
            {
                const float dx = ax - c0.w, dy = ay - c1.x, dz = az - c1.y;
                const float d2 = fmaf(dx, dx, fmaf(dy, dy, dz * dz));
                v += (lab.y == al) ? d2 : fmaxf(0.0f, MARGIN - d2);
            }
            {
                const float dx = ax - c1.z, dy = ay - c1.w, dz = az - c2.x;
                const float d2 = fmaf(dx, dx, fmaf(dy, dy, dz * dz));
                v += (lab.z == al) ? d2 : fmaxf(0.0f, MARGIN - d2);
            }
            {
                const float dx = ax - c2.y, dy = ay - c2.z, dz = az - c2.w;
                const float d2 = fmaf(dx, dx, fmaf(dy, dy, dz * dz));
                v += (lab.w == al) ? d2 : fmaxf(0.0f, MARGIN - d2);
            }
        } else {
            for (int i = base; i < n; i++) {
                const float dx = ax - coords[3 * i + 0];
                const float dy = ay - coords[3 * i + 1];
                const float dz = az - coords[3 * i + 2];
                const float d2 = fmaf(dx, dx, fmaf(dy, dy, dz * dz));
                v += (labels[i] == al) ? d2 : fmaxf(0.0f, MARGIN - d2);
            }
        }
    }

    // ---- Block reduce: warp shfl -> smem -> warp0 shfl ----
    #pragma unroll
    for (int o = 16; o > 0; o >>= 1)
        v += __shfl_down_sync(0xFFFFFFFFu, v, o);

    __shared__ float s[TPB / 32];
    const int lane = threadIdx.x & 31;
    const int wid  = threadIdx.x >> 5;
    if (lane == 0) s[wid] = v;
    __syncthreads();

    if (wid == 0) {
        v = s[lane];                       // TPB/32 == 32, all lanes valid
        #pragma unroll
        for (int o = 16; o > 0; o >>= 1)
            v += __shfl_down_sync(0xFFFFFFFFu, v, o);

        if (lane == 0) {
            if (blockIdx.x != 0) {
                // Publish: RED partial, then release-count (orders the RED).
                red_add_f32_relaxed(&g_accum, v);
                red_add_u32_release(&g_count, 1u);
            } else {
                // Finisher: spin overlaps the other CTAs' completion.
                while (ld_u32_acquire(&g_count) != (unsigned)(NBLOCKS - 1)) { }
                const float others = ld_f32_relaxed(&g_accum);
                out[0] = others + v;
                // Reset for the next replay (visible at kernel boundary).
                st_f32_relaxed(&g_accum, 0.0f);
                st_u32_relaxed(&g_count, 0u);
            }
        }
    }
}

extern "C" void kernel_launch(void* const* d_in, const int* in_sizes, int n_in,
                              void* d_out, int out_size)
{
    const int*   labels = (const int*)d_in[0];
    const float* coords = (const float*)d_in[1];
    float*       out    = (float*)d_out;
    const int n = in_sizes[0];

    contrastive_last_anchor_kernel<<<NBLOCKS, TPB>>>(labels, coords, out, n);
}

// round 14
// speedup vs baseline: 1.1731x; 1.1731x over previous
#include <cuda_runtime.h>
#include <cuda_bf16.h>

// loss_i = (label_i == label[N-1]) ? d2 : max(0, MARGIN - d2),  d2 = ||p_{N-1}-p_i||^2, D=3
// Output: scalar sum. SINGLE graph node, 64 CTAs x 128 threads (one CTA/SM,
// single wave, all CTAs co-resident -> spin cannot deadlock). Body = measured
// best (R9): wide batched loads, 5-shfl warp reduce, one fire-and-forget RED
// per warp leader into a device accumulator + release arrival-count. All warps
// exit immediately. Exactly one thread (CTA0/T0) spin-waits with nanosleep
// backoff (overlapping the stragglers), combines, writes out[0], and resets
// the globals for the next graph replay. Allocation-free, graph-capturable,
// deterministic work per call.

#define MARGIN 500.0f
#define TPB 128
#define PTS_PER_THREAD 4

__device__ float        g_accum = 0.0f;
__device__ unsigned int g_count = 0u;

__device__ __forceinline__ void red_add_f32_relaxed(float* p, float v) {
    asm volatile("red.relaxed.gpu.add.f32 [%0], %1;" :: "l"(p), "f"(v) : "memory");
}
__device__ __forceinline__ void red_add_u32_release(unsigned* p, unsigned v) {
    asm volatile("red.release.gpu.add.u32 [%0], %1;" :: "l"(p), "r"(v) : "memory");
}
__device__ __forceinline__ unsigned ld_u32_acquire(const unsigned* p) {
    unsigned v;
    asm volatile("ld.acquire.gpu.u32 %0, [%1];" : "=r"(v) : "l"(p) : "memory");
    return v;
}
__device__ __forceinline__ float ld_f32_relaxed(const float* p) {
    float v;
    asm volatile("ld.relaxed.gpu.f32 %0, [%1];" : "=f"(v) : "l"(p) : "memory");
    return v;
}
__device__ __forceinline__ void st_u32_relaxed(unsigned* p, unsigned v) {
    asm volatile("st.relaxed.gpu.u32 [%0], %1;" :: "l"(p), "r"(v) : "memory");
}
__device__ __forceinline__ void st_f32_relaxed(float* p, float v) {
    asm volatile("st.relaxed.gpu.f32 [%0], %1;" :: "l"(p), "f"(v) : "memory");
}

__global__ __launch_bounds__(TPB)
void contrastive_last_anchor_kernel(const int* __restrict__ labels,
                                    const float* __restrict__ coords,
                                    float* __restrict__ out,
                                    int n, unsigned int total_warps)
{
    const int t    = blockIdx.x * TPB + threadIdx.x;
    const int base = t * PTS_PER_THREAD;

    // ---- All wide loads issued up front (independent -> batched MLP) ----
    int4   lab = make_int4(0, 0, 0, 0);
    float4 c0 = make_float4(0.f, 0.f, 0.f, 0.f);
    float4 c1 = c0, c2 = c0;
    const bool full = (base + PTS_PER_THREAD <= n);
    if (full) {
        lab = *reinterpret_cast<const int4*>(labels + base);                    // 16B aligned
        const float4* cp = reinterpret_cast<const float4*>(coords + 3 * base);  // 48B/thread -> 16B aligned
        c0 = cp[0]; c1 = cp[1]; c2 = cp[2];
    }

    // Anchor: same 2 cache lines chip-wide -> broadcast; overlaps loads above.
    const int   al = __ldg(labels + (n - 1));
    const float ax = __ldg(coords + 3 * (n - 1) + 0);
    const float ay = __ldg(coords + 3 * (n - 1) + 1);
    const float az = __ldg(coords + 3 * (n - 1) + 2);

    float v = 0.0f;
    if (full) {
        // p0=(c0.x,c0.y,c0.z) p1=(c0.w,c1.x,c1.y) p2=(c1.z,c1.w,c2.x) p3=(c2.y,c2.z,c2.w)
        {
            const float dx = ax - c0.x, dy = ay - c0.y, dz = az - c0.z;
            const float d2 = fmaf(dx, dx, fmaf(dy, dy, dz * dz));
            v += (lab.x == al) ? d2 : fmaxf(0.0f, MARGIN - d2);
        }
        {
            const float dx = ax - c0.w, dy = ay - c1.x, dz = az - c1.y;
            const float d2 = fmaf(dx, dx, fmaf(dy, dy, dz * dz));
            v += (lab.y == al) ? d2 : fmaxf(0.0f, MARGIN - d2);
        }
        {
            const float dx = ax - c1.z, dy = ay - c1.w, dz = az - c2.x;
            const float d2 = fmaf(dx, dx, fmaf(dy, dy, dz * dz));
            v += (lab.z == al) ? d2 : fmaxf(0.0f, MARGIN - d2);
        }
        {
            const float dx = ax - c2.y, dy = ay - c2.z, dz = az - c2.w;
            const float d2 = fmaf(dx, dx, fmaf(dy, dy, dz * dz));
            v += (lab.w == al) ? d2 : fmaxf(0.0f, MARGIN - d2);
        }
    } else {
        for (int i = base; i < n && i < base + PTS_PER_THREAD; i++) {
            const float dx = ax - coords[3 * i + 0];
            const float dy = ay - coords[3 * i + 1];
            const float dz = az - coords[3 * i + 2];
            const float d2 = fmaf(dx, dx, fmaf(dy, dy, dz * dz));
            v += (labels[i] == al) ? d2 : fmaxf(0.0f, MARGIN - d2);
        }
    }

    // ---- Warp reduce (5 shfl), then fire-and-forget publish per warp ----
    #pragma unroll
    for (int o = 16; o > 0; o >>= 1)
        v += __shfl_down_sync(0xFFFFFFFFu, v, o);

    if ((threadIdx.x & 31) == 0) {
        red_add_f32_relaxed(&g_accum, v);    // no return -> no dependent chain
        red_add_u32_release(&g_count, 1u);   // release orders the RED above
    }

    // ---- Single finisher thread: spin (with backoff) overlaps stragglers ----
    if (blockIdx.x == 0 && threadIdx.x == 0) {
        while (ld_u32_acquire(&g_count) != total_warps) {
            __nanosleep(32);
        }
        out[0] = ld_f32_relaxed(&g_accum);
        // Reset for the next graph replay (visible at kernel boundary).
        st_f32_relaxed(&g_accum, 0.0f);
        st_u32_relaxed(&g_count, 0u);
    }
}

extern "C" void kernel_launch(void* const* d_in, const int* in_sizes, int n_in,
                              void* d_out, int out_size)
{
    const int*   labels = (const int*)d_in[0];
    const float* coords = (const float*)d_in[1];
    float*       out    = (float*)d_out;
    const int n = in_sizes[0];

    const int pts_per_cta = TPB * PTS_PER_THREAD;                 // 512
    const int blocks = (n + pts_per_cta - 1) / pts_per_cta;       // 64 for n=32768
    const unsigned total_warps = (unsigned)blocks * (TPB / 32);   // 256

    contrastive_last_anchor_kernel<<<blocks, TPB>>>(labels, coords, out, n, total_warps);
}